// round 1
// baseline (speedup 1.0000x reference)
#include <cuda_runtime.h>
#include <math.h>

// ---------------- problem constants ----------------
#define NR 2000
#define NP 1512
#define NM 3512            // NR + NP
#define K_ATT 3000
#define K_FUN 5603
#define H_ATT 2048
#define H_FUN 4096
#define NSAMP 8192

#define E_P_OFS  ((size_t)NR * 512)                 // 1,024,000
#define OUT_OFS  (E_P_OFS + (size_t)NP * 512)       // 1,798,144
#define FLAT_OFS (OUT_OFS + (size_t)NSAMP * 2)      // 1,814,528

// ---------------- scratch (no allocations allowed) ----------------
__device__ float g_h_att[(size_t)NM * H_ATT];   // 3512 x 2048
__device__ float g_h_fun[(size_t)NM * H_FUN];   // 3512 x 4096

// conv weights/biases in constant memory (uniform-broadcast access pattern)
__constant__ float c_w1[240];    // [16][3][5]
__constant__ float c_b1[16];
__constant__ float c_w2[7680];   // [32][16][3][5]
__constant__ float c_b2[32];
__constant__ float c_bout[2];

__device__ __forceinline__ float gelu_exact(float x) {
    return 0.5f * x * (1.0f + erff(x * 0.70710678118654752440f));
}

// ---------------- SGEMM: C = act(A @ W + b) ----------------
// A is a virtual concat of A0 (n_r rows) and A1 (M-n_r rows), both row-major [*,K].
// ACT==0: gelu, store to Cplain [M,N].
// ACT==1: sigmoid, scatter into d_out e_r/e_p layout at column offset col_ofs.
template<int ACT>
__global__ void __launch_bounds__(256)
gemm_kernel(const float* __restrict__ A0, const float* __restrict__ A1, int n_r,
            const float* __restrict__ W, const float* __restrict__ bias,
            int M, int N, int K,
            float* __restrict__ Cplain, float* __restrict__ outbase, int col_ofs)
{
    __shared__ float As[8][128];   // transposed A tile
    __shared__ float Bs[8][128];

    const int tid = threadIdx.x;
    const int bm = blockIdx.y * 128;
    const int bn = blockIdx.x * 128;
    const int tr = (tid / 16) * 8;
    const int tc = (tid % 16) * 8;

    const int a_m  = tid >> 1;          // 0..127
    const int a_k0 = (tid & 1) * 4;     // 0 or 4
    const int b_k  = tid >> 5;          // 0..7
    const int b_n0 = (tid * 4) & 127;

    const int arow = bm + a_m;
    const float* Arow = 0;
    if (arow < M)
        Arow = (arow < n_r) ? (A0 + (size_t)arow * K)
                            : (A1 + (size_t)(arow - n_r) * K);

    float acc[8][8];
#pragma unroll
    for (int i = 0; i < 8; i++)
#pragma unroll
        for (int j = 0; j < 8; j++) acc[i][j] = 0.f;

    for (int k0 = 0; k0 < K; k0 += 8) {
#pragma unroll
        for (int i = 0; i < 4; i++) {
            int k = k0 + a_k0 + i;
            As[a_k0 + i][a_m] = (Arow && k < K) ? __ldg(Arow + k) : 0.f;
        }
        {
            int kb = k0 + b_k;
            bool kok = kb < K;
            const float* Wp = W + (size_t)kb * N + bn + b_n0;
#pragma unroll
            for (int i = 0; i < 4; i++) {
                int n = bn + b_n0 + i;
                Bs[b_k][b_n0 + i] = (kok && n < N) ? __ldg(Wp + i) : 0.f;
            }
        }
        __syncthreads();
#pragma unroll
        for (int kk = 0; kk < 8; kk++) {
            float4 a0 = *(const float4*)&As[kk][tr];
            float4 a1 = *(const float4*)&As[kk][tr + 4];
            float4 b0 = *(const float4*)&Bs[kk][tc];
            float4 b1 = *(const float4*)&Bs[kk][tc + 4];
            float ra[8] = {a0.x, a0.y, a0.z, a0.w, a1.x, a1.y, a1.z, a1.w};
            float rb[8] = {b0.x, b0.y, b0.z, b0.w, b1.x, b1.y, b1.z, b1.w};
#pragma unroll
            for (int i = 0; i < 8; i++)
#pragma unroll
                for (int j = 0; j < 8; j++)
                    acc[i][j] += ra[i] * rb[j];
        }
        __syncthreads();
    }

#pragma unroll
    for (int i = 0; i < 8; i++) {
        int m = bm + tr + i;
        if (m >= M) break;
#pragma unroll
        for (int j = 0; j < 8; j++) {
            int n = bn + tc + j;
            if (n >= N) continue;
            float v = acc[i][j] + bias[n];
            if (ACT == 0) {
                Cplain[(size_t)m * N + n] = gelu_exact(v);
            } else {
                v = 1.f / (1.f + expf(-v));
                size_t dst = (m < NR)
                    ? ((size_t)m * 512 + col_ofs + n)
                    : (E_P_OFS + (size_t)(m - NR) * 512 + col_ofs + n);
                outbase[dst] = v;
            }
        }
    }
}

// ---------------- fused gather + conv1/pool + conv2/pool + tanh + out GEMV ----------------
// One block (256 thr) per sample. All intermediates in SMEM.
__global__ void __launch_bounds__(256)
conv_kernel(const int* __restrict__ idx, const float* __restrict__ W_out,
            float* __restrict__ d_out)
{
    __shared__ float xp[2][516];        // input rows with halo (index iw+2)
    __shared__ float h1p[16][2][260];   // pooled conv1 with halo (index pw+2)
    __shared__ float red[16];

    const int s = blockIdx.x;
    const int tid = threadIdx.x;
    const int w = tid >> 5, l = tid & 31;

    const int id = idx[s];
    const int r_no = id / 1512;
    const int p_no = id % 1512;
    const float* er = d_out + (size_t)r_no * 512;
    const float* ep = d_out + E_P_OFS + (size_t)p_no * 512;

    for (int t = tid; t < 2 * 516; t += 256) {
        int row = (t >= 516);
        int c = row ? (t - 516) : t;
        int iw = c - 2;
        float v = 0.f;
        if (iw >= 0 && iw < 512) v = row ? ep[iw] : er[iw];
        xp[row][c] = v;
    }
    if (tid < 128) {  // zero h1p halos: cols 0,1,258,259 for each of 16x2 rows
        int ic = tid >> 3, rem = tid & 7;
        int ih = rem >> 2, e = rem & 3;
        int c = (e < 2) ? e : (256 + e);
        h1p[ic][ih][c] = 0.f;
    }
    __syncthreads();

    // ---- conv1 (3x5, pad 2) + leaky + avgpool(2x2): out h1p[16][2][256] ----
    // warp w handles oc in {w, w+8}; lanes cover pooled width.
#pragma unroll
    for (int ph = 0; ph < 2; ph++) {
#pragma unroll
        for (int j = 0; j < 8; j++) {
            int pw = l + 32 * j;
            float t0[6], t1[6];
#pragma unroll
            for (int q = 0; q < 6; q++) { t0[q] = xp[0][2 * pw + q]; t1[q] = xp[1][2 * pw + q]; }
#pragma unroll
            for (int oi = 0; oi < 2; oi++) {
                int oc = w + 8 * oi;
                float b = c_b1[oc];
                float v00 = b, v01 = b, v10 = b, v11 = b;  // v[dh][dw], oh = 2ph+dh
#pragma unroll
                for (int kw = 0; kw < 5; kw++) {
                    float w0 = c_w1[oc * 15 + 0 + kw];
                    float w1 = c_w1[oc * 15 + 5 + kw];
                    float w2 = c_w1[oc * 15 + 10 + kw];
                    if (ph == 0) {
                        // oh=0: (ih0,kh2);  oh=1: (ih0,kh1)+(ih1,kh2)
                        v00 += t0[kw] * w2;                 v01 += t0[kw + 1] * w2;
                        v10 += t0[kw] * w1 + t1[kw] * w2;   v11 += t0[kw + 1] * w1 + t1[kw + 1] * w2;
                    } else {
                        // oh=2: (ih0,kh0)+(ih1,kh1);  oh=3: (ih1,kh0)
                        v00 += t0[kw] * w0 + t1[kw] * w1;   v01 += t0[kw + 1] * w0 + t1[kw + 1] * w1;
                        v10 += t1[kw] * w0;                 v11 += t1[kw + 1] * w0;
                    }
                }
                float lk00 = v00 >= 0.f ? v00 : 0.01f * v00;
                float lk01 = v01 >= 0.f ? v01 : 0.01f * v01;
                float lk10 = v10 >= 0.f ? v10 : 0.01f * v10;
                float lk11 = v11 >= 0.f ? v11 : 0.01f * v11;
                h1p[oc][ph][pw + 2] = 0.25f * (lk00 + lk01 + lk10 + lk11);
            }
        }
    }
    __syncthreads();

    // ---- conv2 (32oc, 16ic, 3x5, pad2) + leaky + maxpool + tanh + flat + out dot ----
    float p0 = 0.f, p1 = 0.f;
#pragma unroll 1
    for (int oig = 0; oig < 2; oig++) {
        float acc[2][4][8];   // [a(oc-pair)][oh][j]
#pragma unroll
        for (int a = 0; a < 2; a++) {
            float b = c_b2[w + 8 * a + 16 * oig];
#pragma unroll
            for (int oh = 0; oh < 4; oh++)
#pragma unroll
                for (int j = 0; j < 8; j++) acc[a][oh][j] = b;
        }
#pragma unroll 1
        for (int ic = 0; ic < 16; ic++) {
            float wg[2][15];
#pragma unroll
            for (int a = 0; a < 2; a++) {
                int oc = w + 8 * a + 16 * oig;
                const float* cw = c_w2 + ((size_t)oc * 16 + ic) * 15;
#pragma unroll
                for (int q = 0; q < 15; q++) wg[a][q] = cw[q];
            }
#pragma unroll
            for (int j = 0; j < 8; j++) {
                int ow = l + 32 * j;
                float u0[5], u1[5];
#pragma unroll
                for (int q = 0; q < 5; q++) { u0[q] = h1p[ic][0][ow + q]; u1[q] = h1p[ic][1][ow + q]; }
#pragma unroll
                for (int a = 0; a < 2; a++) {
#pragma unroll
                    for (int kw = 0; kw < 5; kw++) {
                        float w0 = wg[a][kw], w1 = wg[a][5 + kw], w2 = wg[a][10 + kw];
                        acc[a][0][j] += u0[kw] * w2;                 // oh=0
                        acc[a][1][j] += u0[kw] * w1;                 // oh=1
                        acc[a][1][j] += u1[kw] * w2;
                        acc[a][2][j] += u0[kw] * w0;                 // oh=2
                        acc[a][2][j] += u1[kw] * w1;
                        acc[a][3][j] += u1[kw] * w0;                 // oh=3
                    }
                }
            }
        }
        // maxpool(2x2) over (oh pairs, lane pairs), leaky (monotone -> after max), tanh
#pragma unroll
        for (int a = 0; a < 2; a++) {
            int oc = w + 8 * a + 16 * oig;
#pragma unroll
            for (int ph = 0; ph < 2; ph++) {
#pragma unroll
                for (int j = 0; j < 8; j++) {
                    float m = fmaxf(acc[a][2 * ph][j], acc[a][2 * ph + 1][j]);
                    float o = __shfl_xor_sync(0xffffffffu, m, 1);
                    m = fmaxf(m, o);
                    if ((l & 1) == 0) {
                        float lv = m >= 0.f ? m : 0.01f * m;
                        float val = tanhf(lv);
                        int pw = (l >> 1) + 16 * j;
                        int fidx = oc * 256 + ph * 128 + pw;
                        d_out[FLAT_OFS + (size_t)s * 8192 + fidx] = val;
                        p0 += val * __ldg(W_out + 2 * fidx);
                        p1 += val * __ldg(W_out + 2 * fidx + 1);
                    }
                }
            }
        }
    }

    // reduce output dot across block
#pragma unroll
    for (int off = 16; off > 0; off >>= 1) {
        p0 += __shfl_xor_sync(0xffffffffu, p0, off);
        p1 += __shfl_xor_sync(0xffffffffu, p1, off);
    }
    if (l == 0) { red[w] = p0; red[8 + w] = p1; }
    __syncthreads();
    if (tid == 0) {
        float s0 = c_bout[0], s1 = c_bout[1];
#pragma unroll
        for (int q = 0; q < 8; q++) { s0 += red[q]; s1 += red[8 + q]; }
        d_out[OUT_OFS + 2 * (size_t)s]     = s0;
        d_out[OUT_OFS + 2 * (size_t)s + 1] = s1;
    }
}

// ---------------- launch ----------------
extern "C" void kernel_launch(void* const* d_in, const int* in_sizes, int n_in,
                              void* d_out_, int out_size)
{
    (void)in_sizes; (void)n_in; (void)out_size;
    const float* r_att  = (const float*)d_in[0];
    const float* p_att  = (const float*)d_in[1];
    const float* r_fun  = (const float*)d_in[2];
    const float* p_fun  = (const float*)d_in[3];
    const int*   idx    = (const int*)d_in[4];
    const float* W_att1 = (const float*)d_in[5];
    const float* b_att1 = (const float*)d_in[6];
    const float* W_att2 = (const float*)d_in[7];
    const float* b_att2 = (const float*)d_in[8];
    const float* W_fun1 = (const float*)d_in[9];
    const float* b_fun1 = (const float*)d_in[10];
    const float* W_fun2 = (const float*)d_in[11];
    const float* b_fun2 = (const float*)d_in[12];
    const float* W_out  = (const float*)d_in[17];
    float* d_out = (float*)d_out_;

    cudaMemcpyToSymbolAsync(c_w1,   d_in[13], 240  * sizeof(float), 0, cudaMemcpyDeviceToDevice);
    cudaMemcpyToSymbolAsync(c_b1,   d_in[14], 16   * sizeof(float), 0, cudaMemcpyDeviceToDevice);
    cudaMemcpyToSymbolAsync(c_w2,   d_in[15], 7680 * sizeof(float), 0, cudaMemcpyDeviceToDevice);
    cudaMemcpyToSymbolAsync(c_b2,   d_in[16], 32   * sizeof(float), 0, cudaMemcpyDeviceToDevice);
    cudaMemcpyToSymbolAsync(c_bout, d_in[18], 2    * sizeof(float), 0, cudaMemcpyDeviceToDevice);

    float *h_att_ptr = 0, *h_fun_ptr = 0;
    cudaGetSymbolAddress((void**)&h_att_ptr, g_h_att);
    cudaGetSymbolAddress((void**)&h_fun_ptr, g_h_fun);

    dim3 blk(256);
    {   // att MLP layer 1: gelu -> g_h_att
        dim3 g(H_ATT / 128, (NM + 127) / 128);
        gemm_kernel<0><<<g, blk>>>(r_att, p_att, NR, W_att1, b_att1,
                                   NM, H_ATT, K_ATT, h_att_ptr, 0, 0);
    }
    {   // fun MLP layer 1: gelu -> g_h_fun
        dim3 g(H_FUN / 128, (NM + 127) / 128);
        gemm_kernel<0><<<g, blk>>>(r_fun, p_fun, NR, W_fun1, b_fun1,
                                   NM, H_FUN, K_FUN, h_fun_ptr, 0, 0);
    }
    {   // layer 2s: sigmoid -> scatter into e_r/e_p regions of d_out
        dim3 g(256 / 128, (NM + 127) / 128);
        gemm_kernel<1><<<g, blk>>>(h_att_ptr, h_att_ptr, NM, W_att2, b_att2,
                                   NM, 256, H_ATT, 0, d_out, 0);
        gemm_kernel<1><<<g, blk>>>(h_fun_ptr, h_fun_ptr, NM, W_fun2, b_fun2,
                                   NM, 256, H_FUN, 0, d_out, 256);
    }
    conv_kernel<<<NSAMP, blk>>>(idx, W_out, d_out);
}

// round 3
// speedup vs baseline: 2.0278x; 2.0278x over previous
#include <cuda_runtime.h>
#include <math.h>
#include <stdint.h>

// ---------------- problem constants ----------------
#define NR 2000
#define NP 1512
#define NM 3512            // NR + NP
#define NSAMP 8192
#define SPLITK 4

#define E_P_OFS  ((size_t)NR * 512)                 // 1,024,000
#define OUT_OFS  (E_P_OFS + (size_t)NP * 512)       // 1,798,144
#define FLAT_OFS (OUT_OFS + (size_t)NSAMP * 2)      // 1,814,528

// ---------------- scratch (no allocations allowed) ----------------
__device__ float g_h_att[(size_t)NM * 2048];
__device__ float g_h_fun[(size_t)NM * 4096];
__device__ float g_part_att[(size_t)SPLITK * NM * 256];
__device__ float g_part_fun[(size_t)SPLITK * NM * 256];

// conv weights/biases in constant memory
__constant__ float c_w1[240];    // [16][3][5]
__constant__ float c_b1[16];
__constant__ float c_w2[7680];   // [32][16][3][5]
__constant__ float c_b2[32];
__constant__ float c_bout[2];

__device__ __forceinline__ float gelu_exact(float x) {
    return 0.5f * x * (1.0f + erff(x * 0.70710678118654752440f));
}

// ---------------- async copy + mma helpers ----------------
__device__ __forceinline__ uint32_t sptr(const void* p) {
    return (uint32_t)__cvta_generic_to_shared(p);
}
__device__ __forceinline__ void cpa16(uint32_t d, const void* s, int bytes) {
    asm volatile("cp.async.cg.shared.global [%0], [%1], 16, %2;\n"
                 :: "r"(d), "l"(s), "r"(bytes));
}
__device__ __forceinline__ void cpa4(uint32_t d, const void* s, int bytes) {
    asm volatile("cp.async.ca.shared.global [%0], [%1], 4, %2;\n"
                 :: "r"(d), "l"(s), "r"(bytes));
}
__device__ __forceinline__ void cp_commit() {
    asm volatile("cp.async.commit_group;\n");
}
__device__ __forceinline__ void cp_wait1() {
    asm volatile("cp.async.wait_group 1;\n");
}
__device__ __forceinline__ void mma_tf32(float* d, const uint32_t* a, const uint32_t* b) {
    asm volatile(
        "mma.sync.aligned.m16n8k8.row.col.f32.tf32.tf32.f32 "
        "{%0,%1,%2,%3}, {%4,%5,%6,%7}, {%8,%9}, {%0,%1,%2,%3};\n"
        : "+f"(d[0]), "+f"(d[1]), "+f"(d[2]), "+f"(d[3])
        : "r"(a[0]), "r"(a[1]), "r"(a[2]), "r"(a[3]), "r"(b[0]), "r"(b[1]));
}

// ---------------- tf32 tensor-core GEMM ----------------
// C = act(A @ W + b). A = virtual concat of A0 (n_r rows) then A1, row stride Ktot.
// ACT==0: gelu -> C[M,N].  ACT==2: raw partial -> C + blockIdx.z*M*N (split-K).
// A16: true iff (Ktot*4) % 16 == 0 for BOTH A sources (enables 16B cp.async).
// Tiles: BM=128, BN=128, BK=16. 256 threads (8 warps, 2x4), warp tile 64x32.
// Smem: A as [m][k] stride 20, B transposed as [n][k] stride 20 (conflict-free frags).
#define STAGE_B (128 * 20 * 4)

#define GEMM_LOAD(st, k0)                                                   \
  {                                                                         \
    if (A16) {                                                              \
      _Pragma("unroll")                                                     \
      for (int q = 0; q < 2; q++) {                                         \
        int kq = (k0) + akoff + q * 4;                                      \
        int bytes = aval ? max(0, min(kend - kq, 4)) * 4 : 0;               \
        const float* srcA = Aptr + (bytes ? kq : 0);                        \
        cpa16(sa + (st) * STAGE_B + q * 16, srcA, bytes);                   \
      }                                                                     \
    } else {                                                                \
      _Pragma("unroll")                                                     \
      for (int q = 0; q < 8; q++) {                                         \
        int kq = (k0) + akoff + q;                                          \
        int bytes = (aval && kq < kend) ? 4 : 0;                            \
        const float* srcA = Aptr + (bytes ? kq : 0);                        \
        cpa4(sa + (st) * STAGE_B + q * 4, srcA, bytes);                     \
      }                                                                     \
    }                                                                       \
    _Pragma("unroll")                                                       \
    for (int i = 0; i < 8; i++) {                                           \
      int ko = bkb + ((i + brot) & 7);                                      \
      int kg = (k0) + ko;                                                   \
      int bytes = (kg < kend) ? 4 : 0;                                      \
      const float* srcB = Wc + (size_t)(bytes ? kg : kbeg) * N;             \
      cpa4(sb + (st) * STAGE_B + ko * 4, srcB, bytes);                      \
    }                                                                       \
    cp_commit();                                                            \
  }

template<int ACT, bool A16>
__global__ void __launch_bounds__(256, 2)
gemm_tf32(const float* __restrict__ A0, const float* __restrict__ A1, int n_r,
          const float* __restrict__ W, const float* __restrict__ bias,
          int M, int N, int Ktot, int Kchunk,
          float* __restrict__ C)
{
    __shared__ __align__(16) float As[2][128 * 20];
    __shared__ __align__(16) float Bs[2][128 * 20];

    const int tid  = threadIdx.x;
    const int lane = tid & 31;
    const int warp = tid >> 5;
    const int bm = blockIdx.y * 128;
    const int bn = blockIdx.x * 128;
    const int wm = (warp >> 2) * 64;
    const int wn = (warp & 3) * 32;
    const int kbeg = blockIdx.z * Kchunk;
    const int kend = min(kbeg + Kchunk, Ktot);

    // A loader: thread t -> row t>>1, k-half (t&1)*8
    const int arow = bm + (tid >> 1);
    const bool aval = arow < M;
    const float* Aptr;
    {
        int r = aval ? arow : 0;
        Aptr = (r < n_r) ? (A0 + (size_t)r * Ktot)
                         : (A1 + (size_t)(r - n_r) * Ktot);
    }
    const int akoff = (tid & 1) * 8;
    const uint32_t sa = sptr(&As[0][0]) + ((tid >> 1) * 20 + akoff) * 4;

    // B loader (transpose): thread t -> n = t&127, k-half (t>>7)*8, rotated by n>>3
    const int bnl  = tid & 127;
    const int bkb  = (tid >> 7) * 8;
    const int brot = (bnl >> 3) & 7;
    const uint32_t sb = sptr(&Bs[0][0]) + (bnl * 20) * 4;
    const float* Wc = W + bn + bnl;

    float acc[4][4][4];
#pragma unroll
    for (int i = 0; i < 4; i++)
#pragma unroll
        for (int j = 0; j < 4; j++)
#pragma unroll
            for (int q = 0; q < 4; q++) acc[i][j][q] = 0.f;

    const int fr = lane >> 2;
    const int fc = lane & 3;
    const int nT = (kend - kbeg + 15) >> 4;

    GEMM_LOAD(0, kbeg)

    for (int t = 0; t < nT; t++) {
        if (t + 1 < nT) {
            GEMM_LOAD((t + 1) & 1, kbeg + (t + 1) * 16)
        } else {
            cp_commit();
        }
        cp_wait1();
        __syncthreads();

        const float* as = &As[t & 1][0];
        const float* bs = &Bs[t & 1][0];
#pragma unroll
        for (int kq = 0; kq < 2; kq++) {
            const int col = fc + kq * 8;
            uint32_t af[4][4], bf[4][2];
#pragma unroll
            for (int i = 0; i < 4; i++) {
                const float* p = as + (wm + i * 16 + fr) * 20 + col;
                af[i][0] = __float_as_uint(p[0]);
                af[i][1] = __float_as_uint(p[8 * 20]);
                af[i][2] = __float_as_uint(p[4]);
                af[i][3] = __float_as_uint(p[8 * 20 + 4]);
            }
#pragma unroll
            for (int j = 0; j < 4; j++) {
                const float* p = bs + (wn + j * 8 + fr) * 20 + col;
                bf[j][0] = __float_as_uint(p[0]);
                bf[j][1] = __float_as_uint(p[4]);
            }
#pragma unroll
            for (int i = 0; i < 4; i++)
#pragma unroll
                for (int j = 0; j < 4; j++)
                    mma_tf32(acc[i][j], af[i], bf[j]);
        }
        __syncthreads();
    }

    // epilogue
    float* Cb = C;
    if (ACT == 2) Cb += (size_t)blockIdx.z * M * N;
#pragma unroll
    for (int i = 0; i < 4; i++) {
        const int m0 = bm + wm + i * 16 + fr;
#pragma unroll
        for (int j = 0; j < 4; j++) {
            const int n0 = bn + wn + j * 8 + fc * 2;
            float b0 = 0.f, b1 = 0.f;
            if (ACT == 0) { b0 = bias[n0]; b1 = bias[n0 + 1]; }
            if (m0 < M) {
                float v0 = acc[i][j][0] + b0, v1 = acc[i][j][1] + b1;
                if (ACT == 0) { v0 = gelu_exact(v0); v1 = gelu_exact(v1); }
                Cb[(size_t)m0 * N + n0]     = v0;
                Cb[(size_t)m0 * N + n0 + 1] = v1;
            }
            if (m0 + 8 < M) {
                float v2 = acc[i][j][2] + b0, v3 = acc[i][j][3] + b1;
                if (ACT == 0) { v2 = gelu_exact(v2); v3 = gelu_exact(v3); }
                Cb[(size_t)(m0 + 8) * N + n0]     = v2;
                Cb[(size_t)(m0 + 8) * N + n0 + 1] = v3;
            }
        }
    }
}

// ---------------- layer-2 split-K reduce + bias + sigmoid + scatter ----------------
__global__ void __launch_bounds__(256)
l2_epilogue(const float* __restrict__ pa, const float* __restrict__ pf,
            const float* __restrict__ ba, const float* __restrict__ bf,
            float* __restrict__ d_out)
{
    int t = blockIdx.x * blockDim.x + threadIdx.x;
    if (t >= NM * 128) return;
    int m  = t >> 7;
    int c4 = (t & 127) * 4;
    const float* src;
    const float* bb;
    int c;
    if (c4 < 256) { src = pa + (size_t)m * 256 + c4;         bb = ba; c = c4; }
    else          { src = pf + (size_t)m * 256 + (c4 - 256); bb = bf; c = c4 - 256; }
    float v[4];
#pragma unroll
    for (int q = 0; q < 4; q++) {
        float s = bb[c + q];
#pragma unroll
        for (int sk = 0; sk < SPLITK; sk++)
            s += src[(size_t)sk * NM * 256 + q];
        v[q] = 1.f / (1.f + expf(-s));
    }
    size_t dst = (m < NR) ? ((size_t)m * 512 + c4)
                          : (E_P_OFS + (size_t)(m - NR) * 512 + c4);
    *(float4*)(d_out + dst) = make_float4(v[0], v[1], v[2], v[3]);
}

// ---------------- fused gather + conv1/pool + conv2/pool + tanh + out GEMV ----------------
__global__ void __launch_bounds__(256)
conv_kernel(const int* __restrict__ idx, const float* __restrict__ W_out,
            float* __restrict__ d_out)
{
    __shared__ float xp[2][516];        // input rows with halo (index iw+2)
    __shared__ float h1p[16][2][260];   // pooled conv1 with halo (index pw+2)
    __shared__ float red[16];

    const int s = blockIdx.x;
    const int tid = threadIdx.x;
    const int w = tid >> 5, l = tid & 31;

    const int id = idx[s];
    const int r_no = id / 1512;
    const int p_no = id % 1512;
    const float* er = d_out + (size_t)r_no * 512;
    const float* ep = d_out + E_P_OFS + (size_t)p_no * 512;

    for (int t = tid; t < 2 * 516; t += 256) {
        int row = (t >= 516);
        int c = row ? (t - 516) : t;
        int iw = c - 2;
        float v = 0.f;
        if (iw >= 0 && iw < 512) v = row ? ep[iw] : er[iw];
        xp[row][c] = v;
    }
    if (tid < 128) {
        int ic = tid >> 3, rem = tid & 7;
        int ih = rem >> 2, e = rem & 3;
        int c = (e < 2) ? e : (256 + e);
        h1p[ic][ih][c] = 0.f;
    }
    __syncthreads();

    // ---- conv1 (3x5, pad 2) + leaky + avgpool(2x2) ----
#pragma unroll
    for (int ph = 0; ph < 2; ph++) {
#pragma unroll
        for (int j = 0; j < 8; j++) {
            int pw = l + 32 * j;
            float t0[6], t1[6];
#pragma unroll
            for (int q = 0; q < 6; q++) { t0[q] = xp[0][2 * pw + q]; t1[q] = xp[1][2 * pw + q]; }
#pragma unroll
            for (int oi = 0; oi < 2; oi++) {
                int oc = w + 8 * oi;
                float b = c_b1[oc];
                float v00 = b, v01 = b, v10 = b, v11 = b;
#pragma unroll
                for (int kw = 0; kw < 5; kw++) {
                    float w0 = c_w1[oc * 15 + 0 + kw];
                    float w1 = c_w1[oc * 15 + 5 + kw];
                    float w2 = c_w1[oc * 15 + 10 + kw];
                    if (ph == 0) {
                        v00 += t0[kw] * w2;                 v01 += t0[kw + 1] * w2;
                        v10 += t0[kw] * w1 + t1[kw] * w2;   v11 += t0[kw + 1] * w1 + t1[kw + 1] * w2;
                    } else {
                        v00 += t0[kw] * w0 + t1[kw] * w1;   v01 += t0[kw + 1] * w0 + t1[kw + 1] * w1;
                        v10 += t1[kw] * w0;                 v11 += t1[kw + 1] * w0;
                    }
                }
                float lk00 = v00 >= 0.f ? v00 : 0.01f * v00;
                float lk01 = v01 >= 0.f ? v01 : 0.01f * v01;
                float lk10 = v10 >= 0.f ? v10 : 0.01f * v10;
                float lk11 = v11 >= 0.f ? v11 : 0.01f * v11;
                h1p[oc][ph][pw + 2] = 0.25f * (lk00 + lk01 + lk10 + lk11);
            }
        }
    }
    __syncthreads();

    // ---- conv2 + leaky + maxpool + tanh + flat + out dot ----
    float p0 = 0.f, p1 = 0.f;
#pragma unroll 1
    for (int oig = 0; oig < 2; oig++) {
        float acc[2][4][8];
#pragma unroll
        for (int a = 0; a < 2; a++) {
            float b = c_b2[w + 8 * a + 16 * oig];
#pragma unroll
            for (int oh = 0; oh < 4; oh++)
#pragma unroll
                for (int j = 0; j < 8; j++) acc[a][oh][j] = b;
        }
#pragma unroll 1
        for (int ic = 0; ic < 16; ic++) {
            float wg[2][15];
#pragma unroll
            for (int a = 0; a < 2; a++) {
                int oc = w + 8 * a + 16 * oig;
                const float* cw = c_w2 + ((size_t)oc * 16 + ic) * 15;
#pragma unroll
                for (int q = 0; q < 15; q++) wg[a][q] = cw[q];
            }
#pragma unroll
            for (int j = 0; j < 8; j++) {
                int ow = l + 32 * j;
                float u0[5], u1[5];
#pragma unroll
                for (int q = 0; q < 5; q++) { u0[q] = h1p[ic][0][ow + q]; u1[q] = h1p[ic][1][ow + q]; }
#pragma unroll
                for (int a = 0; a < 2; a++) {
#pragma unroll
                    for (int kw = 0; kw < 5; kw++) {
                        float w0 = wg[a][kw], w1 = wg[a][5 + kw], w2 = wg[a][10 + kw];
                        acc[a][0][j] += u0[kw] * w2;
                        acc[a][1][j] += u0[kw] * w1;
                        acc[a][1][j] += u1[kw] * w2;
                        acc[a][2][j] += u0[kw] * w0;
                        acc[a][2][j] += u1[kw] * w1;
                        acc[a][3][j] += u1[kw] * w0;
                    }
                }
            }
        }
#pragma unroll
        for (int a = 0; a < 2; a++) {
            int oc = w + 8 * a + 16 * oig;
#pragma unroll
            for (int ph = 0; ph < 2; ph++) {
#pragma unroll
                for (int j = 0; j < 8; j++) {
                    float m = fmaxf(acc[a][2 * ph][j], acc[a][2 * ph + 1][j]);
                    float o = __shfl_xor_sync(0xffffffffu, m, 1);
                    m = fmaxf(m, o);
                    if ((l & 1) == 0) {
                        float lv = m >= 0.f ? m : 0.01f * m;
                        float val = tanhf(lv);
                        int pw = (l >> 1) + 16 * j;
                        int fidx = oc * 256 + ph * 128 + pw;
                        d_out[FLAT_OFS + (size_t)s * 8192 + fidx] = val;
                        p0 += val * __ldg(W_out + 2 * fidx);
                        p1 += val * __ldg(W_out + 2 * fidx + 1);
                    }
                }
            }
        }
    }

#pragma unroll
    for (int off = 16; off > 0; off >>= 1) {
        p0 += __shfl_xor_sync(0xffffffffu, p0, off);
        p1 += __shfl_xor_sync(0xffffffffu, p1, off);
    }
    if (l == 0) { red[w] = p0; red[8 + w] = p1; }
    __syncthreads();
    if (tid == 0) {
        float s0 = c_bout[0], s1 = c_bout[1];
#pragma unroll
        for (int q = 0; q < 8; q++) { s0 += red[q]; s1 += red[8 + q]; }
        d_out[OUT_OFS + 2 * (size_t)s]     = s0;
        d_out[OUT_OFS + 2 * (size_t)s + 1] = s1;
    }
}

// ---------------- launch ----------------
extern "C" void kernel_launch(void* const* d_in, const int* in_sizes, int n_in,
                              void* d_out_, int out_size)
{
    (void)in_sizes; (void)n_in; (void)out_size;
    const float* r_att  = (const float*)d_in[0];
    const float* p_att  = (const float*)d_in[1];
    const float* r_fun  = (const float*)d_in[2];
    const float* p_fun  = (const float*)d_in[3];
    const int*   idx    = (const int*)d_in[4];
    const float* W_att1 = (const float*)d_in[5];
    const float* b_att1 = (const float*)d_in[6];
    const float* W_att2 = (const float*)d_in[7];
    const float* b_att2 = (const float*)d_in[8];
    const float* W_fun1 = (const float*)d_in[9];
    const float* b_fun1 = (const float*)d_in[10];
    const float* W_fun2 = (const float*)d_in[11];
    const float* b_fun2 = (const float*)d_in[12];
    const float* W_out  = (const float*)d_in[17];
    float* d_out = (float*)d_out_;

    cudaMemcpyToSymbolAsync(c_w1,   d_in[13], 240  * sizeof(float), 0, cudaMemcpyDeviceToDevice);
    cudaMemcpyToSymbolAsync(c_b1,   d_in[14], 16   * sizeof(float), 0, cudaMemcpyDeviceToDevice);
    cudaMemcpyToSymbolAsync(c_w2,   d_in[15], 7680 * sizeof(float), 0, cudaMemcpyDeviceToDevice);
    cudaMemcpyToSymbolAsync(c_b2,   d_in[16], 32   * sizeof(float), 0, cudaMemcpyDeviceToDevice);
    cudaMemcpyToSymbolAsync(c_bout, d_in[18], 2    * sizeof(float), 0, cudaMemcpyDeviceToDevice);

    float *h_att_p = 0, *h_fun_p = 0, *pa = 0, *pf = 0;
    cudaGetSymbolAddress((void**)&h_att_p, g_h_att);
    cudaGetSymbolAddress((void**)&h_fun_p, g_h_fun);
    cudaGetSymbolAddress((void**)&pa, g_part_att);
    cudaGetSymbolAddress((void**)&pf, g_part_fun);

    dim3 blk(256);
    // layer 1: gelu.  att: K=3000 (rows 16B-aligned).  fun: K=5603 (NOT 16B-aligned!)
    gemm_tf32<0, true ><<<dim3(2048 / 128, 28, 1), blk>>>(r_att, p_att, NR, W_att1, b_att1,
                                                          NM, 2048, 3000, 3000, h_att_p);
    gemm_tf32<0, false><<<dim3(4096 / 128, 28, 1), blk>>>(r_fun, p_fun, NR, W_fun1, b_fun1,
                                                          NM, 4096, 5603, 5603, h_fun_p);
    // layer 2: split-K raw partials (K=2048/4096, 16B-aligned)
    gemm_tf32<2, true><<<dim3(2, 28, SPLITK), blk>>>(h_att_p, h_att_p, NM, W_att2, b_att2,
                                                     NM, 256, 2048, 2048 / SPLITK, pa);
    gemm_tf32<2, true><<<dim3(2, 28, SPLITK), blk>>>(h_fun_p, h_fun_p, NM, W_fun2, b_fun2,
                                                     NM, 256, 4096, 4096 / SPLITK, pf);
    // reduce + bias + sigmoid + scatter to e_r / e_p
    l2_epilogue<<<(NM * 128 + 255) / 256, 256>>>(pa, pf, b_att2, b_fun2, d_out);
    // conv stage
    conv_kernel<<<NSAMP, blk>>>(idx, W_out, d_out);
}

// round 6
// speedup vs baseline: 2.1241x; 1.0475x over previous
#include <cuda_runtime.h>
#include <math.h>
#include <stdint.h>

// ---------------- problem constants ----------------
#define NR 2000
#define NP 1512
#define NM 3512            // NR + NP
#define NSAMP 8192
#define SPLITK 4

#define E_P_OFS  ((size_t)NR * 512)                 // 1,024,000
#define OUT_OFS  (E_P_OFS + (size_t)NP * 512)       // 1,798,144
#define FLAT_OFS (OUT_OFS + (size_t)NSAMP * 2)      // 1,814,528

// ---------------- scratch (no allocations allowed) ----------------
__device__ float g_h_att[(size_t)NM * 2048];
__device__ float g_h_fun[(size_t)NM * 4096];
__device__ float g_part_att[(size_t)SPLITK * NM * 256];
__device__ float g_part_fun[(size_t)SPLITK * NM * 256];

// conv weights/biases in constant memory
__constant__ float c_w1[240];    // [16][3][5]
__constant__ float c_b1[16];
__constant__ float c_w2[7680];   // [32][16][3][5]
__constant__ float c_b2[32];
__constant__ float c_bout[2];

__device__ __forceinline__ float gelu_exact(float x) {
    return 0.5f * x * (1.0f + erff(x * 0.70710678118654752440f));
}

// ---------------- async copy + mma helpers ----------------
__device__ __forceinline__ uint32_t sptr(const void* p) {
    return (uint32_t)__cvta_generic_to_shared(p);
}
__device__ __forceinline__ void cpa16(uint32_t d, const void* s, int bytes) {
    asm volatile("cp.async.cg.shared.global [%0], [%1], 16, %2;\n"
                 :: "r"(d), "l"(s), "r"(bytes));
}
__device__ __forceinline__ void cpa4(uint32_t d, const void* s, int bytes) {
    asm volatile("cp.async.ca.shared.global [%0], [%1], 4, %2;\n"
                 :: "r"(d), "l"(s), "r"(bytes));
}
__device__ __forceinline__ void cp_commit() {
    asm volatile("cp.async.commit_group;\n");
}
__device__ __forceinline__ void cp_wait1() {
    asm volatile("cp.async.wait_group 1;\n");
}
__device__ __forceinline__ void mma_tf32(float* d, const uint32_t* a, const uint32_t* b) {
    asm volatile(
        "mma.sync.aligned.m16n8k8.row.col.f32.tf32.tf32.f32 "
        "{%0,%1,%2,%3}, {%4,%5,%6,%7}, {%8,%9}, {%0,%1,%2,%3};\n"
        : "+f"(d[0]), "+f"(d[1]), "+f"(d[2]), "+f"(d[3])
        : "r"(a[0]), "r"(a[1]), "r"(a[2]), "r"(a[3]), "r"(b[0]), "r"(b[1]));
}

// ---------------- tf32 tensor-core GEMM v2 ----------------
// C = act(A @ W + b). A = virtual concat of A0 (n_r rows) then A1, row stride Ktot.
// ACT==0: gelu -> C[M,N].  ACT==2: raw partial -> C + blockIdx.z*M*N (split-K).
// A16: rows of A are 16B aligned (K*4 % 16 == 0).
// BM=128, BN=256, BK=16. 256 threads = 8 warps (2x4), warp tile 64x64.
// A smem [m][16] with k ^= ((m>>1)&3)<<2  (conflict-free frag LDS, 16B-block safe)
// B smem [k][256] with n ^= (k&3)<<3      (conflict-free frag LDS + cpa16 stores)
// grid: x = m-blocks (L2 slab sharing), y = n-blocks, z = split-K chunk.
#define ASTAGE (128 * 16)
#define BSTAGE (16 * 256)

#define GEMM_LOAD(st, k0)                                                    \
  {                                                                          \
    if (A16) {                                                               \
      _Pragma("unroll")                                                      \
      for (int q = 0; q < 2; q++) {                                          \
        int kq = (k0) + akoff + q * 4;                                       \
        int bytes = aval ? max(0, min(kend - kq, 4)) * 4 : 0;                \
        const float* srcA = Aptr + (bytes ? kq : 0);                         \
        int dw = ambase + ((akoff + q * 4) ^ awz);                           \
        cpa16(sa + ((st) * ASTAGE + dw) * 4, srcA, bytes);                   \
      }                                                                      \
    } else {                                                                 \
      _Pragma("unroll")                                                      \
      for (int q = 0; q < 8; q++) {                                          \
        int kq = (k0) + akoff + q;                                           \
        int bytes = (aval && kq < kend) ? 4 : 0;                             \
        const float* srcA = Aptr + (bytes ? kq : 0);                         \
        int dw = ambase + ((akoff + q) ^ awz);                               \
        cpa4(sa + ((st) * ASTAGE + dw) * 4, srcA, bytes);                    \
      }                                                                      \
    }                                                                        \
    {                                                                        \
      int kg = (k0) + bk;                                                    \
      int bytes = (kg < kend) ? 16 : 0;                                      \
      const float* srcB = W + (size_t)(bytes ? kg : kbeg) * N + bn + bn0;    \
      _Pragma("unroll")                                                      \
      for (int q = 0; q < 4; q++) {                                          \
        int dw = bk * 256 + ((bn0 + q * 4) ^ bswz);                          \
        cpa16(sb + ((st) * BSTAGE + dw) * 4, srcB + q * 4, bytes);           \
      }                                                                      \
    }                                                                        \
    cp_commit();                                                             \
  }

template<int ACT, bool A16>
__global__ void __launch_bounds__(256, 1)
gemm_tf32(const float* __restrict__ A0, const float* __restrict__ A1, int n_r,
          const float* __restrict__ W, const float* __restrict__ bias,
          int M, int N, int Ktot, int Kchunk,
          float* __restrict__ C)
{
    __shared__ __align__(16) float As[2][ASTAGE];
    __shared__ __align__(16) float Bs[2][BSTAGE];

    const int tid  = threadIdx.x;
    const int lane = tid & 31;
    const int warp = tid >> 5;
    const int bm = blockIdx.x * 128;
    const int bn = blockIdx.y * 256;
    const int wm = (warp >> 2) * 64;
    const int wn = (warp & 3) * 64;
    const int kbeg = blockIdx.z * Kchunk;
    const int kend = min(kbeg + Kchunk, Ktot);

    // A loader: thread t -> row t>>1, k-half (t&1)*8
    const int am = tid >> 1;
    const int arow = bm + am;
    const bool aval = arow < M;
    const float* Aptr;
    {
        int r = aval ? arow : 0;
        Aptr = (r < n_r) ? (A0 + (size_t)r * Ktot)
                         : (A1 + (size_t)(r - n_r) * Ktot);
    }
    const int akoff  = (tid & 1) * 8;
    const int ambase = am * 16;
    const int awz    = ((am >> 1) & 3) << 2;
    const uint32_t sa = sptr(&As[0][0]);

    // B loader: thread t -> k row t>>4, n block (t&15)*16
    const int bk   = tid >> 4;
    const int bn0  = (tid & 15) * 16;
    const int bswz = (bk & 3) << 3;
    const uint32_t sb = sptr(&Bs[0][0]);

    float acc[4][8][4];
#pragma unroll
    for (int i = 0; i < 4; i++)
#pragma unroll
        for (int j = 0; j < 8; j++)
#pragma unroll
            for (int q = 0; q < 4; q++) acc[i][j][q] = 0.f;

    const int fr = lane >> 2;
    const int fc = lane & 3;
    const int nT = (kend - kbeg + 15) >> 4;

    GEMM_LOAD(0, kbeg)

    for (int t = 0; t < nT; t++) {
        if (t + 1 < nT) {
            GEMM_LOAD((t + 1) & 1, kbeg + (t + 1) * 16)
        } else {
            cp_commit();
        }
        cp_wait1();
        __syncthreads();

        const float* as = &As[t & 1][0];
        const float* bs = &Bs[t & 1][0];
#pragma unroll
        for (int kq = 0; kq < 2; kq++) {
            uint32_t af[4][4], bf[8][2];
#pragma unroll
            for (int i = 0; i < 4; i++) {
                const int row = wm + i * 16 + fr;
                const int swz = ((row >> 1) & 3) << 2;
                const float* p  = as + row * 16;
                const float* p8 = as + (row + 8) * 16;
                const int c0 = (fc + kq * 8) ^ swz;
                const int c4 = (fc + 4 + kq * 8) ^ swz;
                af[i][0] = __float_as_uint(p[c0]);
                af[i][1] = __float_as_uint(p8[c0]);
                af[i][2] = __float_as_uint(p[c4]);
                af[i][3] = __float_as_uint(p8[c4]);
            }
#pragma unroll
            for (int j = 0; j < 8; j++) {
                const int n = (wn + j * 8 + fr) ^ (fc << 3);
                bf[j][0] = __float_as_uint(bs[(fc + kq * 8) * 256 + n]);
                bf[j][1] = __float_as_uint(bs[(fc + 4 + kq * 8) * 256 + n]);
            }
#pragma unroll
            for (int i = 0; i < 4; i++)
#pragma unroll
                for (int j = 0; j < 8; j++)
                    mma_tf32(acc[i][j], af[i], bf[j]);
        }
        __syncthreads();
    }

    // epilogue
    float* Cb = C;
    if (ACT == 2) Cb += (size_t)blockIdx.z * M * N;
#pragma unroll
    for (int i = 0; i < 4; i++) {
        const int m0 = bm + wm + i * 16 + fr;
#pragma unroll
        for (int j = 0; j < 8; j++) {
            const int n0 = bn + wn + j * 8 + fc * 2;
            float b0 = 0.f, b1 = 0.f;
            if (ACT == 0) { b0 = bias[n0]; b1 = bias[n0 + 1]; }
            if (m0 < M) {
                float v0 = acc[i][j][0] + b0, v1 = acc[i][j][1] + b1;
                if (ACT == 0) { v0 = gelu_exact(v0); v1 = gelu_exact(v1); }
                Cb[(size_t)m0 * N + n0]     = v0;
                Cb[(size_t)m0 * N + n0 + 1] = v1;
            }
            if (m0 + 8 < M) {
                float v2 = acc[i][j][2] + b0, v3 = acc[i][j][3] + b1;
                if (ACT == 0) { v2 = gelu_exact(v2); v3 = gelu_exact(v3); }
                Cb[(size_t)(m0 + 8) * N + n0]     = v2;
                Cb[(size_t)(m0 + 8) * N + n0 + 1] = v3;
            }
        }
    }
}

// ---------------- layer-2 split-K reduce + bias + sigmoid + scatter ----------------
__global__ void __launch_bounds__(256)
l2_epilogue(const float* __restrict__ pa, const float* __restrict__ pf,
            const float* __restrict__ ba, const float* __restrict__ bf,
            float* __restrict__ d_out)
{
    int t = blockIdx.x * blockDim.x + threadIdx.x;
    if (t >= NM * 128) return;
    int m  = t >> 7;
    int c4 = (t & 127) * 4;
    const float* src;
    const float* bb;
    int c;
    if (c4 < 256) { src = pa + (size_t)m * 256 + c4;         bb = ba; c = c4; }
    else          { src = pf + (size_t)m * 256 + (c4 - 256); bb = bf; c = c4 - 256; }
    float v[4];
#pragma unroll
    for (int q = 0; q < 4; q++) {
        float s = bb[c + q];
#pragma unroll
        for (int sk = 0; sk < SPLITK; sk++)
            s += src[(size_t)sk * NM * 256 + q];
        v[q] = 1.f / (1.f + expf(-s));
    }
    size_t dst = (m < NR) ? ((size_t)m * 512 + c4)
                          : (E_P_OFS + (size_t)(m - NR) * 512 + c4);
    *(float4*)(d_out + dst) = make_float4(v[0], v[1], v[2], v[3]);
}

// ---------------- fused gather + conv1/pool + conv2/pool + tanh + out GEMV ----------------
__global__ void __launch_bounds__(256)
conv_kernel(const int* __restrict__ idx, const float* __restrict__ W_out,
            float* __restrict__ d_out)
{
    __shared__ float xp[2][516];        // input rows with halo (index iw+2)
    __shared__ float h1p[16][2][260];   // pooled conv1 with halo (index pw+2)
    __shared__ float red[16];

    const int s = blockIdx.x;
    const int tid = threadIdx.x;
    const int w = tid >> 5, l = tid & 31;

    const int id = idx[s];
    const int r_no = id / 1512;
    const int p_no = id % 1512;
    const float* er = d_out + (size_t)r_no * 512;
    const float* ep = d_out + E_P_OFS + (size_t)p_no * 512;

    for (int t = tid; t < 2 * 516; t += 256) {
        int row = (t >= 516);
        int c = row ? (t - 516) : t;
        int iw = c - 2;
        float v = 0.f;
        if (iw >= 0 && iw < 512) v = row ? ep[iw] : er[iw];
        xp[row][c] = v;
    }
    if (tid < 128) {
        int ic = tid >> 3, rem = tid & 7;
        int ih = rem >> 2, e = rem & 3;
        int c = (e < 2) ? e : (256 + e);
        h1p[ic][ih][c] = 0.f;
    }
    __syncthreads();

    // ---- conv1 (3x5, pad 2) + leaky + avgpool(2x2) ----
#pragma unroll
    for (int ph = 0; ph < 2; ph++) {
#pragma unroll
        for (int j = 0; j < 8; j++) {
            int pw = l + 32 * j;
            float t0[6], t1[6];
#pragma unroll
            for (int q = 0; q < 6; q++) { t0[q] = xp[0][2 * pw + q]; t1[q] = xp[1][2 * pw + q]; }
#pragma unroll
            for (int oi = 0; oi < 2; oi++) {
                int oc = w + 8 * oi;
                float b = c_b1[oc];
                float v00 = b, v01 = b, v10 = b, v11 = b;
#pragma unroll
                for (int kw = 0; kw < 5; kw++) {
                    float w0 = c_w1[oc * 15 + 0 + kw];
                    float w1 = c_w1[oc * 15 + 5 + kw];
                    float w2 = c_w1[oc * 15 + 10 + kw];
                    if (ph == 0) {
                        v00 += t0[kw] * w2;                 v01 += t0[kw + 1] * w2;
                        v10 += t0[kw] * w1 + t1[kw] * w2;   v11 += t0[kw + 1] * w1 + t1[kw + 1] * w2;
                    } else {
                        v00 += t0[kw] * w0 + t1[kw] * w1;   v01 += t0[kw + 1] * w0 + t1[kw + 1] * w1;
                        v10 += t1[kw] * w0;                 v11 += t1[kw + 1] * w0;
                    }
                }
                float lk00 = v00 >= 0.f ? v00 : 0.01f * v00;
                float lk01 = v01 >= 0.f ? v01 : 0.01f * v01;
                float lk10 = v10 >= 0.f ? v10 : 0.01f * v10;
                float lk11 = v11 >= 0.f ? v11 : 0.01f * v11;
                h1p[oc][ph][pw + 2] = 0.25f * (lk00 + lk01 + lk10 + lk11);
            }
        }
    }
    __syncthreads();

    // ---- conv2 + leaky + maxpool + tanh + flat + out dot ----
    float p0 = 0.f, p1 = 0.f;
#pragma unroll 1
    for (int oig = 0; oig < 2; oig++) {
        float acc[2][4][8];
#pragma unroll
        for (int a = 0; a < 2; a++) {
            float b = c_b2[w + 8 * a + 16 * oig];
#pragma unroll
            for (int oh = 0; oh < 4; oh++)
#pragma unroll
                for (int j = 0; j < 8; j++) acc[a][oh][j] = b;
        }
#pragma unroll 1
        for (int ic = 0; ic < 16; ic++) {
            float wg[2][15];
#pragma unroll
            for (int a = 0; a < 2; a++) {
                int oc = w + 8 * a + 16 * oig;
                const float* cw = c_w2 + ((size_t)oc * 16 + ic) * 15;
#pragma unroll
                for (int q = 0; q < 15; q++) wg[a][q] = cw[q];
            }
#pragma unroll
            for (int j = 0; j < 8; j++) {
                int ow = l + 32 * j;
                float u0[5], u1[5];
#pragma unroll
                for (int q = 0; q < 5; q++) { u0[q] = h1p[ic][0][ow + q]; u1[q] = h1p[ic][1][ow + q]; }
#pragma unroll
                for (int a = 0; a < 2; a++) {
#pragma unroll
                    for (int kw = 0; kw < 5; kw++) {
                        float w0 = wg[a][kw], w1 = wg[a][5 + kw], w2 = wg[a][10 + kw];
                        acc[a][0][j] += u0[kw] * w2;
                        acc[a][1][j] += u0[kw] * w1;
                        acc[a][1][j] += u1[kw] * w2;
                        acc[a][2][j] += u0[kw] * w0;
                        acc[a][2][j] += u1[kw] * w1;
                        acc[a][3][j] += u1[kw] * w0;
                    }
                }
            }
        }
#pragma unroll
        for (int a = 0; a < 2; a++) {
            int oc = w + 8 * a + 16 * oig;
#pragma unroll
            for (int ph = 0; ph < 2; ph++) {
#pragma unroll
                for (int j = 0; j < 8; j++) {
                    float m = fmaxf(acc[a][2 * ph][j], acc[a][2 * ph + 1][j]);
                    float o = __shfl_xor_sync(0xffffffffu, m, 1);
                    m = fmaxf(m, o);
                    if ((l & 1) == 0) {
                        float lv = m >= 0.f ? m : 0.01f * m;
                        float val = tanhf(lv);
                        int pw = (l >> 1) + 16 * j;
                        int fidx = oc * 256 + ph * 128 + pw;
                        d_out[FLAT_OFS + (size_t)s * 8192 + fidx] = val;
                        p0 += val * __ldg(W_out + 2 * fidx);
                        p1 += val * __ldg(W_out + 2 * fidx + 1);
                    }
                }
            }
        }
    }

#pragma unroll
    for (int off = 16; off > 0; off >>= 1) {
        p0 += __shfl_xor_sync(0xffffffffu, p0, off);
        p1 += __shfl_xor_sync(0xffffffffu, p1, off);
    }
    if (l == 0) { red[w] = p0; red[8 + w] = p1; }
    __syncthreads();
    if (tid == 0) {
        float s0 = c_bout[0], s1 = c_bout[1];
#pragma unroll
        for (int q = 0; q < 8; q++) { s0 += red[q]; s1 += red[8 + q]; }
        d_out[OUT_OFS + 2 * (size_t)s]     = s0;
        d_out[OUT_OFS + 2 * (size_t)s + 1] = s1;
    }
}

// ---------------- launch ----------------
extern "C" void kernel_launch(void* const* d_in, const int* in_sizes, int n_in,
                              void* d_out_, int out_size)
{
    (void)in_sizes; (void)n_in; (void)out_size;
    const float* r_att  = (const float*)d_in[0];
    const float* p_att  = (const float*)d_in[1];
    const float* r_fun  = (const float*)d_in[2];
    const float* p_fun  = (const float*)d_in[3];
    const int*   idx    = (const int*)d_in[4];
    const float* W_att1 = (const float*)d_in[5];
    const float* b_att1 = (const float*)d_in[6];
    const float* W_att2 = (const float*)d_in[7];
    const float* b_att2 = (const float*)d_in[8];
    const float* W_fun1 = (const float*)d_in[9];
    const float* b_fun1 = (const float*)d_in[10];
    const float* W_fun2 = (const float*)d_in[11];
    const float* b_fun2 = (const float*)d_in[12];
    const float* W_out  = (const float*)d_in[17];
    float* d_out = (float*)d_out_;

    cudaMemcpyToSymbolAsync(c_w1,   d_in[13], 240  * sizeof(float), 0, cudaMemcpyDeviceToDevice);
    cudaMemcpyToSymbolAsync(c_b1,   d_in[14], 16   * sizeof(float), 0, cudaMemcpyDeviceToDevice);
    cudaMemcpyToSymbolAsync(c_w2,   d_in[15], 7680 * sizeof(float), 0, cudaMemcpyDeviceToDevice);
    cudaMemcpyToSymbolAsync(c_b2,   d_in[16], 32   * sizeof(float), 0, cudaMemcpyDeviceToDevice);
    cudaMemcpyToSymbolAsync(c_bout, d_in[18], 2    * sizeof(float), 0, cudaMemcpyDeviceToDevice);

    float *h_att_p = 0, *h_fun_p = 0, *pa = 0, *pf = 0;
    cudaGetSymbolAddress((void**)&h_att_p, g_h_att);
    cudaGetSymbolAddress((void**)&h_fun_p, g_h_fun);
    cudaGetSymbolAddress((void**)&pa, g_part_att);
    cudaGetSymbolAddress((void**)&pf, g_part_fun);

    dim3 blk(256);
    // layer 1: gelu.  grid.x = m-blocks (28), grid.y = n-blocks.
    gemm_tf32<0, true ><<<dim3(28, 2048 / 256, 1), blk>>>(r_att, p_att, NR, W_att1, b_att1,
                                                          NM, 2048, 3000, 3000, h_att_p);
    gemm_tf32<0, false><<<dim3(28, 4096 / 256, 1), blk>>>(r_fun, p_fun, NR, W_fun1, b_fun1,
                                                          NM, 4096, 5603, 5603, h_fun_p);
    // layer 2: split-K raw partials (N=256 -> single n-block)
    gemm_tf32<2, true><<<dim3(28, 1, SPLITK), blk>>>(h_att_p, h_att_p, NM, W_att2, b_att2,
                                                     NM, 256, 2048, 2048 / SPLITK, pa);
    gemm_tf32<2, true><<<dim3(28, 1, SPLITK), blk>>>(h_fun_p, h_fun_p, NM, W_fun2, b_fun2,
                                                     NM, 256, 4096, 4096 / SPLITK, pf);
    // reduce + bias + sigmoid + scatter to e_r / e_p
    l2_epilogue<<<(NM * 128 + 255) / 256, 256>>>(pa, pf, b_att2, b_fun2, d_out);
    // conv stage
    conv_kernel<<<NSAMP, blk>>>(idx, W_out, d_out);
}

// round 7
// speedup vs baseline: 2.3758x; 1.1185x over previous
#include <cuda_runtime.h>
#include <math.h>
#include <stdint.h>

// ---------------- problem constants ----------------
#define NR 2000
#define NP 1512
#define NM 3512            // NR + NP
#define NSAMP 8192
#define SPLITK 4

#define E_P_OFS  ((size_t)NR * 512)                 // 1,024,000
#define OUT_OFS  (E_P_OFS + (size_t)NP * 512)       // 1,798,144
#define FLAT_OFS (OUT_OFS + (size_t)NSAMP * 2)      // 1,814,528

typedef unsigned long long ull;

// ---------------- scratch (no allocations allowed) ----------------
__device__ float g_h_att[(size_t)NM * 2048];
__device__ float g_h_fun[(size_t)NM * 4096];
__device__ float g_part_att[(size_t)SPLITK * NM * 256];
__device__ float g_part_fun[(size_t)SPLITK * NM * 256];

// conv weights/biases in constant memory
__constant__ float c_w1[240];    // [16][3][5]
__constant__ float c_b1[16];
__constant__ float c_w2[7680];   // [32][16][3][5]
__constant__ float c_b2[32];
__constant__ float c_bout[2];

__device__ __forceinline__ float gelu_exact(float x) {
    return 0.5f * x * (1.0f + erff(x * 0.70710678118654752440f));
}

// ---------------- packed f32x2 helpers (sm_103a) ----------------
__device__ __forceinline__ ull packf2(float lo, float hi) {
    ull r; asm("mov.b64 %0, {%1,%2};" : "=l"(r) : "f"(lo), "f"(hi)); return r;
}
__device__ __forceinline__ void unpackf2(ull v, float& lo, float& hi) {
    asm("mov.b64 {%0,%1}, %2;" : "=f"(lo), "=f"(hi) : "l"(v));
}
__device__ __forceinline__ void ffma2(ull& d, ull a, ull b) {
    asm("fma.rn.f32x2 %0, %1, %2, %0;" : "+l"(d) : "l"(a), "l"(b));
}

// ---------------- async copy + mma helpers ----------------
__device__ __forceinline__ uint32_t sptr(const void* p) {
    return (uint32_t)__cvta_generic_to_shared(p);
}
__device__ __forceinline__ void cpa16(uint32_t d, const void* s, int bytes) {
    asm volatile("cp.async.cg.shared.global [%0], [%1], 16, %2;\n"
                 :: "r"(d), "l"(s), "r"(bytes));
}
__device__ __forceinline__ void cpa4(uint32_t d, const void* s, int bytes) {
    asm volatile("cp.async.ca.shared.global [%0], [%1], 4, %2;\n"
                 :: "r"(d), "l"(s), "r"(bytes));
}
__device__ __forceinline__ void cp_commit() {
    asm volatile("cp.async.commit_group;\n");
}
__device__ __forceinline__ void cp_wait1() {
    asm volatile("cp.async.wait_group 1;\n");
}
__device__ __forceinline__ void mma_tf32(float* d, const uint32_t* a, const uint32_t* b) {
    asm volatile(
        "mma.sync.aligned.m16n8k8.row.col.f32.tf32.tf32.f32 "
        "{%0,%1,%2,%3}, {%4,%5,%6,%7}, {%8,%9}, {%0,%1,%2,%3};\n"
        : "+f"(d[0]), "+f"(d[1]), "+f"(d[2]), "+f"(d[3])
        : "r"(a[0]), "r"(a[1]), "r"(a[2]), "r"(a[3]), "r"(b[0]), "r"(b[1]));
}

// ---------------- tf32 tensor-core GEMM v3 ----------------
// C = act(A @ W + b). A = virtual concat of A0 (n_r rows) then A1, row stride Ktot.
// ACT==0: gelu -> C[M,N].  ACT==2: raw partial -> C + blockIdx.z*M*N (split-K).
// BM=128, BN=128, BK=16. 256 threads = 8 warps (4m x 2n), warp tile 32x64.
// 2 CTAs/SM (regs <= 128) for latency hiding.
// A smem [m][16] with k ^= ((m>>1)&3)<<2 ; B smem [k][128] with n ^= (k&3)<<3.
#define ASTAGE (128 * 16)
#define BSTAGE (16 * 128)

#define GEMM_LOAD(st, k0)                                                    \
  {                                                                          \
    if (A16) {                                                               \
      _Pragma("unroll")                                                      \
      for (int q = 0; q < 2; q++) {                                          \
        int kq = (k0) + akoff + q * 4;                                       \
        int bytes = aval ? max(0, min(kend - kq, 4)) * 4 : 0;                \
        const float* srcA = Aptr + (bytes ? kq : 0);                         \
        int dw = ambase + ((akoff + q * 4) ^ awz);                           \
        cpa16(sa + ((st) * ASTAGE + dw) * 4, srcA, bytes);                   \
      }                                                                      \
    } else {                                                                 \
      _Pragma("unroll")                                                      \
      for (int q = 0; q < 8; q++) {                                          \
        int kq = (k0) + akoff + q;                                           \
        int bytes = (aval && kq < kend) ? 4 : 0;                             \
        const float* srcA = Aptr + (bytes ? kq : 0);                         \
        int dw = ambase + ((akoff + q) ^ awz);                               \
        cpa4(sa + ((st) * ASTAGE + dw) * 4, srcA, bytes);                    \
      }                                                                      \
    }                                                                        \
    {                                                                        \
      int kg = (k0) + bk;                                                    \
      int bytes = (kg < kend) ? 16 : 0;                                      \
      const float* srcB = W + (size_t)(bytes ? kg : kbeg) * N + bn + bn0;    \
      _Pragma("unroll")                                                      \
      for (int q = 0; q < 2; q++) {                                          \
        int dw = bk * 128 + ((bn0 + q * 4) ^ bswz);                          \
        cpa16(sb + ((st) * BSTAGE + dw) * 4, srcB + q * 4, bytes);           \
      }                                                                      \
    }                                                                        \
    cp_commit();                                                             \
  }

template<int ACT, bool A16>
__global__ void __launch_bounds__(256, 2)
gemm_tf32(const float* __restrict__ A0, const float* __restrict__ A1, int n_r,
          const float* __restrict__ W, const float* __restrict__ bias,
          int M, int N, int Ktot, int Kchunk,
          float* __restrict__ C)
{
    __shared__ __align__(16) float As[2][ASTAGE];
    __shared__ __align__(16) float Bs[2][BSTAGE];

    const int tid  = threadIdx.x;
    const int lane = tid & 31;
    const int warp = tid >> 5;
    const int bm = blockIdx.x * 128;
    const int bn = blockIdx.y * 128;
    const int wm = (warp & 3) * 32;
    const int wn = (warp >> 2) * 64;
    const int kbeg = blockIdx.z * Kchunk;
    const int kend = min(kbeg + Kchunk, Ktot);

    // A loader: thread t -> row t>>1, k-half (t&1)*8
    const int am = tid >> 1;
    const int arow = bm + am;
    const bool aval = arow < M;
    const float* Aptr;
    {
        int r = aval ? arow : 0;
        Aptr = (r < n_r) ? (A0 + (size_t)r * Ktot)
                         : (A1 + (size_t)(r - n_r) * Ktot);
    }
    const int akoff  = (tid & 1) * 8;
    const int ambase = am * 16;
    const int awz    = ((am >> 1) & 3) << 2;
    const uint32_t sa = sptr(&As[0][0]);

    // B loader: thread t -> k row t>>4, n block (t&15)*8
    const int bk   = tid >> 4;
    const int bn0  = (tid & 15) * 8;
    const int bswz = (bk & 3) << 3;
    const uint32_t sb = sptr(&Bs[0][0]);

    float acc[2][8][4];
#pragma unroll
    for (int i = 0; i < 2; i++)
#pragma unroll
        for (int j = 0; j < 8; j++)
#pragma unroll
            for (int q = 0; q < 4; q++) acc[i][j][q] = 0.f;

    const int fr = lane >> 2;
    const int fc = lane & 3;
    const int nT = (kend - kbeg + 15) >> 4;

    GEMM_LOAD(0, kbeg)

    for (int t = 0; t < nT; t++) {
        if (t + 1 < nT) {
            GEMM_LOAD((t + 1) & 1, kbeg + (t + 1) * 16)
        } else {
            cp_commit();
        }
        cp_wait1();
        __syncthreads();

        const float* as = &As[t & 1][0];
        const float* bs = &Bs[t & 1][0];
#pragma unroll
        for (int kq = 0; kq < 2; kq++) {
            uint32_t af[2][4], bf[8][2];
#pragma unroll
            for (int i = 0; i < 2; i++) {
                const int row = wm + i * 16 + fr;
                const int swz = ((row >> 1) & 3) << 2;
                const float* p  = as + row * 16;
                const float* p8 = as + (row + 8) * 16;
                const int c0 = (fc + kq * 8) ^ swz;
                const int c4 = (fc + 4 + kq * 8) ^ swz;
                af[i][0] = __float_as_uint(p[c0]);
                af[i][1] = __float_as_uint(p8[c0]);
                af[i][2] = __float_as_uint(p[c4]);
                af[i][3] = __float_as_uint(p8[c4]);
            }
#pragma unroll
            for (int j = 0; j < 8; j++) {
                const int n = (wn + j * 8 + fr) ^ (fc << 3);
                bf[j][0] = __float_as_uint(bs[(fc + kq * 8) * 128 + n]);
                bf[j][1] = __float_as_uint(bs[(fc + 4 + kq * 8) * 128 + n]);
            }
#pragma unroll
            for (int i = 0; i < 2; i++)
#pragma unroll
                for (int j = 0; j < 8; j++)
                    mma_tf32(acc[i][j], af[i], bf[j]);
        }
        __syncthreads();
    }

    // epilogue
    float* Cb = C;
    if (ACT == 2) Cb += (size_t)blockIdx.z * M * N;
#pragma unroll
    for (int i = 0; i < 2; i++) {
        const int m0 = bm + wm + i * 16 + fr;
#pragma unroll
        for (int j = 0; j < 8; j++) {
            const int n0 = bn + wn + j * 8 + fc * 2;
            float b0 = 0.f, b1 = 0.f;
            if (ACT == 0) { b0 = bias[n0]; b1 = bias[n0 + 1]; }
            if (m0 < M) {
                float v0 = acc[i][j][0] + b0, v1 = acc[i][j][1] + b1;
                if (ACT == 0) { v0 = gelu_exact(v0); v1 = gelu_exact(v1); }
                Cb[(size_t)m0 * N + n0]     = v0;
                Cb[(size_t)m0 * N + n0 + 1] = v1;
            }
            if (m0 + 8 < M) {
                float v2 = acc[i][j][2] + b0, v3 = acc[i][j][3] + b1;
                if (ACT == 0) { v2 = gelu_exact(v2); v3 = gelu_exact(v3); }
                Cb[(size_t)(m0 + 8) * N + n0]     = v2;
                Cb[(size_t)(m0 + 8) * N + n0 + 1] = v3;
            }
        }
    }
}

// ---------------- layer-2 split-K reduce + bias + sigmoid + scatter ----------------
__global__ void __launch_bounds__(256)
l2_epilogue(const float* __restrict__ pa, const float* __restrict__ pf,
            const float* __restrict__ ba, const float* __restrict__ bf,
            float* __restrict__ d_out)
{
    int t = blockIdx.x * blockDim.x + threadIdx.x;
    if (t >= NM * 128) return;
    int m  = t >> 7;
    int c4 = (t & 127) * 4;
    const float* src;
    const float* bb;
    int c;
    if (c4 < 256) { src = pa + (size_t)m * 256 + c4;         bb = ba; c = c4; }
    else          { src = pf + (size_t)m * 256 + (c4 - 256); bb = bf; c = c4 - 256; }
    float v[4];
#pragma unroll
    for (int q = 0; q < 4; q++) {
        float s = bb[c + q];
#pragma unroll
        for (int sk = 0; sk < SPLITK; sk++)
            s += src[(size_t)sk * NM * 256 + q];
        v[q] = 1.f / (1.f + expf(-s));
    }
    size_t dst = (m < NR) ? ((size_t)m * 512 + c4)
                          : (E_P_OFS + (size_t)(m - NR) * 512 + c4);
    *(float4*)(d_out + dst) = make_float4(v[0], v[1], v[2], v[3]);
}

// ---------------- fused gather + conv1/pool + conv2(f32x2)/pool + tanh + out GEMV ----------------
__global__ void __launch_bounds__(256)
conv_kernel(const int* __restrict__ idx, const float* __restrict__ W_out,
            float* __restrict__ d_out)
{
    __shared__ float xp[2][516];        // input rows with halo (index iw+2)
    __shared__ float h1p[16][2][260];   // pooled conv1 with halo (index pw+2)
    __shared__ float red[16];

    const int s = blockIdx.x;
    const int tid = threadIdx.x;
    const int w = tid >> 5, l = tid & 31;

    const int id = idx[s];
    const int r_no = id / 1512;
    const int p_no = id % 1512;
    const float* er = d_out + (size_t)r_no * 512;
    const float* ep = d_out + E_P_OFS + (size_t)p_no * 512;

    for (int t = tid; t < 2 * 516; t += 256) {
        int row = (t >= 516);
        int c = row ? (t - 516) : t;
        int iw = c - 2;
        float v = 0.f;
        if (iw >= 0 && iw < 512) v = row ? ep[iw] : er[iw];
        xp[row][c] = v;
    }
    if (tid < 128) {
        int ic = tid >> 3, rem = tid & 7;
        int ih = rem >> 2, e = rem & 3;
        int c = (e < 2) ? e : (256 + e);
        h1p[ic][ih][c] = 0.f;
    }
    __syncthreads();

    // ---- conv1 (3x5, pad 2) + leaky + avgpool(2x2) ----
#pragma unroll
    for (int ph = 0; ph < 2; ph++) {
#pragma unroll
        for (int j = 0; j < 8; j++) {
            int pw = l + 32 * j;
            float t0[6], t1[6];
#pragma unroll
            for (int q = 0; q < 6; q++) { t0[q] = xp[0][2 * pw + q]; t1[q] = xp[1][2 * pw + q]; }
#pragma unroll
            for (int oi = 0; oi < 2; oi++) {
                int oc = w + 8 * oi;
                float b = c_b1[oc];
                float v00 = b, v01 = b, v10 = b, v11 = b;
#pragma unroll
                for (int kw = 0; kw < 5; kw++) {
                    float w0 = c_w1[oc * 15 + 0 + kw];
                    float w1 = c_w1[oc * 15 + 5 + kw];
                    float w2 = c_w1[oc * 15 + 10 + kw];
                    if (ph == 0) {
                        v00 += t0[kw] * w2;                 v01 += t0[kw + 1] * w2;
                        v10 += t0[kw] * w1 + t1[kw] * w2;   v11 += t0[kw + 1] * w1 + t1[kw + 1] * w2;
                    } else {
                        v00 += t0[kw] * w0 + t1[kw] * w1;   v01 += t0[kw + 1] * w0 + t1[kw + 1] * w1;
                        v10 += t1[kw] * w0;                 v11 += t1[kw + 1] * w0;
                    }
                }
                float lk00 = v00 >= 0.f ? v00 : 0.01f * v00;
                float lk01 = v01 >= 0.f ? v01 : 0.01f * v01;
                float lk10 = v10 >= 0.f ? v10 : 0.01f * v10;
                float lk11 = v11 >= 0.f ? v11 : 0.01f * v11;
                h1p[oc][ph][pw + 2] = 0.25f * (lk00 + lk01 + lk10 + lk11);
            }
        }
    }
    __syncthreads();

    // ---- conv2 (packed f32x2: output pairs (j, j+4)) + leaky + maxpool + tanh + out dot ----
    float p0 = 0.f, p1 = 0.f;
#pragma unroll 1
    for (int oig = 0; oig < 2; oig++) {
        ull accp[2][4][4];   // [a][oh][jp], pair = (j=jp, j=jp+4)
#pragma unroll
        for (int a = 0; a < 2; a++) {
            float b = c_b2[w + 8 * a + 16 * oig];
            ull bp = packf2(b, b);
#pragma unroll
            for (int oh = 0; oh < 4; oh++)
#pragma unroll
                for (int jp = 0; jp < 4; jp++) accp[a][oh][jp] = bp;
        }
#pragma unroll 1
        for (int ic = 0; ic < 16; ic++) {
            ull wgp[2][15];
#pragma unroll
            for (int a = 0; a < 2; a++) {
                int oc = w + 8 * a + 16 * oig;
                const float* cw = c_w2 + ((size_t)oc * 16 + ic) * 15;
#pragma unroll
                for (int q = 0; q < 15; q++) { float c = cw[q]; wgp[a][q] = packf2(c, c); }
            }
#pragma unroll
            for (int jp = 0; jp < 4; jp++) {
                int owA = l + 32 * jp;
                int owB = owA + 128;
                ull pu0[5], pu1[5];
#pragma unroll
                for (int q = 0; q < 5; q++) {
                    pu0[q] = packf2(h1p[ic][0][owA + q], h1p[ic][0][owB + q]);
                    pu1[q] = packf2(h1p[ic][1][owA + q], h1p[ic][1][owB + q]);
                }
#pragma unroll
                for (int a = 0; a < 2; a++) {
#pragma unroll
                    for (int kw = 0; kw < 5; kw++) {
                        ull w0 = wgp[a][kw], w1 = wgp[a][5 + kw], w2 = wgp[a][10 + kw];
                        ffma2(accp[a][0][jp], pu0[kw], w2);
                        ffma2(accp[a][1][jp], pu0[kw], w1);
                        ffma2(accp[a][1][jp], pu1[kw], w2);
                        ffma2(accp[a][2][jp], pu0[kw], w0);
                        ffma2(accp[a][2][jp], pu1[kw], w1);
                        ffma2(accp[a][3][jp], pu1[kw], w0);
                    }
                }
            }
        }
        // maxpool(2x2) + leaky + tanh + store + out-dot.  lo half -> j=jp, hi -> j=jp+4.
#pragma unroll
        for (int a = 0; a < 2; a++) {
            int oc = w + 8 * a + 16 * oig;
#pragma unroll
            for (int ph = 0; ph < 2; ph++) {
#pragma unroll
                for (int jp = 0; jp < 4; jp++) {
                    float lo0, hi0, lo1, hi1;
                    unpackf2(accp[a][2 * ph][jp],     lo0, hi0);
                    unpackf2(accp[a][2 * ph + 1][jp], lo1, hi1);
#pragma unroll
                    for (int half = 0; half < 2; half++) {
                        int j = jp + 4 * half;
                        float m = half ? fmaxf(hi0, hi1) : fmaxf(lo0, lo1);
                        float o = __shfl_xor_sync(0xffffffffu, m, 1);
                        m = fmaxf(m, o);
                        if ((l & 1) == 0) {
                            float lv = m >= 0.f ? m : 0.01f * m;
                            float val = tanhf(lv);
                            int pw = (l >> 1) + 16 * j;
                            int fidx = oc * 256 + ph * 128 + pw;
                            d_out[FLAT_OFS + (size_t)s * 8192 + fidx] = val;
                            p0 += val * __ldg(W_out + 2 * fidx);
                            p1 += val * __ldg(W_out + 2 * fidx + 1);
                        }
                    }
                }
            }
        }
    }

#pragma unroll
    for (int off = 16; off > 0; off >>= 1) {
        p0 += __shfl_xor_sync(0xffffffffu, p0, off);
        p1 += __shfl_xor_sync(0xffffffffu, p1, off);
    }
    if (l == 0) { red[w] = p0; red[8 + w] = p1; }
    __syncthreads();
    if (tid == 0) {
        float s0 = c_bout[0], s1 = c_bout[1];
#pragma unroll
        for (int q = 0; q < 8; q++) { s0 += red[q]; s1 += red[8 + q]; }
        d_out[OUT_OFS + 2 * (size_t)s]     = s0;
        d_out[OUT_OFS + 2 * (size_t)s + 1] = s1;
    }
}

// ---------------- launch ----------------
extern "C" void kernel_launch(void* const* d_in, const int* in_sizes, int n_in,
                              void* d_out_, int out_size)
{
    (void)in_sizes; (void)n_in; (void)out_size;
    const float* r_att  = (const float*)d_in[0];
    const float* p_att  = (const float*)d_in[1];
    const float* r_fun  = (const float*)d_in[2];
    const float* p_fun  = (const float*)d_in[3];
    const int*   idx    = (const int*)d_in[4];
    const float* W_att1 = (const float*)d_in[5];
    const float* b_att1 = (const float*)d_in[6];
    const float* W_att2 = (const float*)d_in[7];
    const float* b_att2 = (const float*)d_in[8];
    const float* W_fun1 = (const float*)d_in[9];
    const float* b_fun1 = (const float*)d_in[10];
    const float* W_fun2 = (const float*)d_in[11];
    const float* b_fun2 = (const float*)d_in[12];
    const float* W_out  = (const float*)d_in[17];
    float* d_out = (float*)d_out_;

    cudaMemcpyToSymbolAsync(c_w1,   d_in[13], 240  * sizeof(float), 0, cudaMemcpyDeviceToDevice);
    cudaMemcpyToSymbolAsync(c_b1,   d_in[14], 16   * sizeof(float), 0, cudaMemcpyDeviceToDevice);
    cudaMemcpyToSymbolAsync(c_w2,   d_in[15], 7680 * sizeof(float), 0, cudaMemcpyDeviceToDevice);
    cudaMemcpyToSymbolAsync(c_b2,   d_in[16], 32   * sizeof(float), 0, cudaMemcpyDeviceToDevice);
    cudaMemcpyToSymbolAsync(c_bout, d_in[18], 2    * sizeof(float), 0, cudaMemcpyDeviceToDevice);

    float *h_att_p = 0, *h_fun_p = 0, *pa = 0, *pf = 0;
    cudaGetSymbolAddress((void**)&h_att_p, g_h_att);
    cudaGetSymbolAddress((void**)&h_fun_p, g_h_fun);
    cudaGetSymbolAddress((void**)&pa, g_part_att);
    cudaGetSymbolAddress((void**)&pf, g_part_fun);

    dim3 blk(256);
    // layer 1: gelu.  grid.x = m-blocks (28), grid.y = n-blocks (BN=128).
    gemm_tf32<0, true ><<<dim3(28, 2048 / 128, 1), blk>>>(r_att, p_att, NR, W_att1, b_att1,
                                                          NM, 2048, 3000, 3000, h_att_p);
    gemm_tf32<0, false><<<dim3(28, 4096 / 128, 1), blk>>>(r_fun, p_fun, NR, W_fun1, b_fun1,
                                                          NM, 4096, 5603, 5603, h_fun_p);
    // layer 2: split-K raw partials (N=256 -> 2 n-blocks)
    gemm_tf32<2, true><<<dim3(28, 2, SPLITK), blk>>>(h_att_p, h_att_p, NM, W_att2, b_att2,
                                                     NM, 256, 2048, 2048 / SPLITK, pa);
    gemm_tf32<2, true><<<dim3(28, 2, SPLITK), blk>>>(h_fun_p, h_fun_p, NM, W_fun2, b_fun2,
                                                     NM, 256, 4096, 4096 / SPLITK, pf);
    // reduce + bias + sigmoid + scatter to e_r / e_p
    l2_epilogue<<<(NM * 128 + 255) / 256, 256>>>(pa, pf, b_att2, b_fun2, d_out);
    // conv stage
    conv_kernel<<<NSAMP, blk>>>(idx, W_out, d_out);
}